// round 10
// baseline (speedup 1.0000x reference)
#include <cuda_runtime.h>

#define NU 100000
#define NI 50000
#define NN 150000
#define HD 64
#define NE 1200000
#define SCAN_B 1024
#define NBLK ((NN + SCAN_B - 1) / SCAN_B)   // 147

typedef unsigned long long ull;

// Scratch (static device globals; zero-initialized at load)
__device__ float g_bufA[NN * HD];
__device__ float g_bufB[NN * HD];
__device__ float g_u1[NN];
__device__ float g_u2[NN];
__device__ float g_dinv[NN];
__device__ int   g_cnt[NN];          // edge in-degree (self loop NOT included)
__device__ int   g_flag[NBLK];       // scan: total+1 (0 = not ready)
__device__ int   g_off[NN + 1];
__device__ int   g_cur[NN];
__device__ int2  g_edge[NE];         // {src, norm bits}, bucketed by dst
__device__ float g_W123[HD * HD];    // W1@W2@W3
__device__ float g_bv1[HD];          // b2@W3
__device__ float g_bv2[HD];          // b1@W2@W3

#define FMA2(acc, a, b) \
    asm("fma.rn.f32x2 %0, %1, %2, %0;" : "+l"(acc) : "l"(a), "l"(b))
#define MUL2(d, a, b) \
    asm("mul.rn.f32x2 %0, %1, %2;" : "=l"(d) : "l"(a), "l"(b))
#define DUPF(d, f) \
    asm("mov.b64 %0, {%1, %1};" : "=l"(d) : "f"(f))
#define DUPR(d, r) \
    asm("mov.b64 %0, {%1, %1};" : "=l"(d) : "r"(r))

// ---------------------------------------------------------------------------
// Degree count
// ---------------------------------------------------------------------------
__global__ void k_deg(const int* __restrict__ ei) {
    int e = blockIdx.x * blockDim.x + threadIdx.x;
    if (e < NE) atomicAdd(&g_cnt[ei[NE + e]], 1);
}

// ---------------------------------------------------------------------------
// Fused: blocks 0..NBLK-1 = single-pass scan of g_cnt (all co-resident,
// decoupled-lookback-lite via g_flag) + dinv; block NBLK = weight products.
// ---------------------------------------------------------------------------
__global__ void __launch_bounds__(1024)
k_scan_wprod(const float* __restrict__ Wsrc, const float* __restrict__ bs) {
    __shared__ float smem[3 * 4096 + 64];
    int tid = threadIdx.x;

    if (blockIdx.x < NBLK) {
        // ---- scan part ----
        int* ws    = (int*)smem;
        int* basep = (int*)smem + 40;
        if (tid == 0) *basep = 0;
        int i = blockIdx.x * SCAN_B + tid;
        int lane = tid & 31, wid = tid >> 5;
        int cnt = (i < NN) ? g_cnt[i] : 0;
        if (i < NN) g_dinv[i] = rsqrtf((float)(cnt + 1));
        int x = cnt;
        #pragma unroll
        for (int o = 1; o < 32; o <<= 1) {
            int y = __shfl_up_sync(0xffffffffu, x, o);
            if (lane >= o) x += y;
        }
        if (lane == 31) ws[wid] = x;
        __syncthreads();
        if (wid == 0) {
            int s = ws[lane];
            #pragma unroll
            for (int o = 1; o < 32; o <<= 1) {
                int y = __shfl_up_sync(0xffffffffu, s, o);
                if (lane >= o) s += y;
            }
            ws[lane] = s;
        }
        __syncthreads();
        int incl = x + (wid > 0 ? ws[wid - 1] : 0);

        if (tid == SCAN_B - 1)
            *((volatile int*)&g_flag[blockIdx.x]) = incl + 1;

        if (tid < blockIdx.x) {
            int v;
            do { v = *((volatile int*)&g_flag[tid]); } while (v == 0);
            atomicAdd(basep, v - 1);
        }
        __syncthreads();

        if (i < NN) {
            int g = incl + *basep;
            g_off[i + 1] = g;
            g_cur[i] = g - cnt;
            if (i == 0) g_off[0] = 0;
        }
    } else {
        // ---- wprod part: W123 = W1@W2@W3, bv2 = b1@W2@W3, bv1 = b2@W3 ----
        float* A = smem;
        float* B = smem + 4096;
        float* T = smem + 8192;
        ((float4*)A)[tid] = ((const float4*)(Wsrc + 4096))[tid];   // W2
        ((float4*)B)[tid] = ((const float4*)(Wsrc + 8192))[tid];   // W3
        __syncthreads();
        #pragma unroll
        for (int i = 0; i < 4; i++) {            // T = W2@W3
            int idx = tid * 4 + i, r = idx >> 6, c = idx & 63;
            float s = 0.f;
            #pragma unroll
            for (int k = 0; k < 64; k++) s += A[r * 64 + k] * B[k * 64 + c];
            T[idx] = s;
        }
        __syncthreads();
        ((float4*)A)[tid] = ((const float4*)Wsrc)[tid];            // W1
        __syncthreads();
        #pragma unroll
        for (int i = 0; i < 4; i++) {            // W123 = W1@T
            int idx = tid * 4 + i, r = idx >> 6, c = idx & 63;
            float s = 0.f;
            #pragma unroll
            for (int k = 0; k < 64; k++) s += A[r * 64 + k] * T[k * 64 + c];
            g_W123[idx] = s;
        }
        if (tid < 64) {                          // bv2 = b1@T
            float s = 0.f;
            #pragma unroll
            for (int k = 0; k < 64; k++) s += bs[k] * T[k * 64 + tid];
            g_bv2[tid] = s;
        } else if (tid < 128) {                  // bv1 = b2@W3
            int c = tid - 64;
            float s = 0.f;
            #pragma unroll
            for (int k = 0; k < 64; k++) s += bs[64 + k] * B[k * 64 + c];
            g_bv1[c] = s;
        }
    }
}

// ---------------------------------------------------------------------------
// Bucket fill (norm from precomputed dinv)
// ---------------------------------------------------------------------------
__global__ void k_fill(const int* __restrict__ ei) {
    int e = blockIdx.x * blockDim.x + threadIdx.x;
    if (e >= NE) return;
    int s = ei[e];
    int d = ei[NE + e];
    float nrm = g_dinv[s] * g_dinv[d];
    int pos = atomicAdd(&g_cur[d], 1);
    g_edge[pos] = make_int2(s, __float_as_int(nrm));
}

// ---------------------------------------------------------------------------
// Aggregation: y[i] = inv_i * x[i] + sum_e nrm_e * x[src_e]
// 8 threads/node (4 nodes/warp). Lane c owns cols [4c,4c+4) and [32+4c,+4)
// (one contiguous 128B line per group per load). Edges fetched by BROADCAST
// load (all 8 lanes same address) — no shuffles, no padding waste.
// ---------------------------------------------------------------------------
template<bool SPLIT, bool UIN, bool UOUT>
__global__ void k_agg(const float* __restrict__ xA, const float* __restrict__ xB,
                      const float* __restrict__ u_in, float* __restrict__ u_out,
                      float* __restrict__ y) {
    int t = blockIdx.x * blockDim.x + threadIdx.x;
    int node = t >> 3;
    int c = t & 7;
    if (node >= NN) return;
    unsigned gmask = 0xFFu << (threadIdx.x & 24);

    int beg = g_off[node];
    int end = g_off[node + 1];
    float inv = 1.0f / (float)(end - beg + 1);
    ull pinv; DUPF(pinv, inv);

    const float* selfp = SPLIT ? (node < NU ? xA + (size_t)node * 64
                                            : xB + (size_t)(node - NU) * 64)
                               : xA + (size_t)node * 64;
    ulonglong2 s0 = *(const ulonglong2*)(selfp + c * 4);
    ulonglong2 s1 = *(const ulonglong2*)(selfp + 32 + c * 4);
    ull acc0, acc1, acc2, acc3;
    MUL2(acc0, s0.x, pinv); MUL2(acc1, s0.y, pinv);
    MUL2(acc2, s1.x, pinv); MUL2(acc3, s1.y, pinv);
    float uacc = 0.0f;

    #pragma unroll 4
    for (int j = beg; j < end; j++) {
        int2 ed = __ldg(&g_edge[j]);             // 8-lane broadcast
        ull ww; DUPR(ww, (unsigned)ed.y);
        const float* hp = SPLIT ? (ed.x < NU ? xA + (size_t)ed.x * 64
                                             : xB + (size_t)(ed.x - NU) * 64)
                                : xA + (size_t)ed.x * 64;
        ulonglong2 h0 = *(const ulonglong2*)(hp + c * 4);
        ulonglong2 h1 = *(const ulonglong2*)(hp + 32 + c * 4);
        FMA2(acc0, ww, h0.x); FMA2(acc1, ww, h0.y);
        FMA2(acc2, ww, h1.x); FMA2(acc3, ww, h1.y);
        if (UOUT && (((j - beg) & 7) == c))      // distribute u loads over lanes
            uacc += __int_as_float(ed.y) * (UIN ? u_in[ed.x] : 1.0f);
    }

    *(ulonglong2*)(y + (size_t)node * 64 + c * 4)      = make_ulonglong2(acc0, acc1);
    *(ulonglong2*)(y + (size_t)node * 64 + 32 + c * 4) = make_ulonglong2(acc2, acc3);

    if (UOUT) {
        #pragma unroll
        for (int o = 4; o > 0; o >>= 1)
            uacc += __shfl_down_sync(gmask, uacc, o, 8);
        if (c == 0) u_out[node] = uacc + inv * (UIN ? u_in[node] : 1.0f);
    }
}

// ---------------------------------------------------------------------------
// Fused agg3 + final GEMM:
//   y3 = A~ @ x staged in smem; out[remap] = y3@W123 + u2*bv2 + u1*bv1 + b3.
// Also copies raw embeddings to out segments 1/3 and re-zeroes g_cnt/g_flag.
// 256 threads = 32 nodes x 8 lanes; GEMM reuses the same row mapping.
// ---------------------------------------------------------------------------
__global__ void k_agg_gemm(const float* __restrict__ x, const float* __restrict__ b3,
                           const float* __restrict__ ue, const float* __restrict__ ie,
                           float* __restrict__ out) {
    __shared__ float Ws[64 * 64];
    __shared__ float Xs[32 * 68];
    int tid  = threadIdx.x;
    int row0 = blockIdx.x * 32;
    int r = tid >> 3;
    int c = tid & 7;
    int node = row0 + r;

    #pragma unroll
    for (int i = 0; i < 4; i++)
        ((float4*)Ws)[tid + i * 256] = ((const float4*)g_W123)[tid + i * 256];

    if (blockIdx.x == 0 && tid < NBLK) g_flag[tid] = 0;

    if (node < NN) {
        // ---- aggregation into smem row ----
        int beg = g_off[node];
        int end = g_off[node + 1];
        float inv = 1.0f / (float)(end - beg + 1);
        ull pinv; DUPF(pinv, inv);

        const float* selfp = x + (size_t)node * 64;
        ulonglong2 s0 = *(const ulonglong2*)(selfp + c * 4);
        ulonglong2 s1 = *(const ulonglong2*)(selfp + 32 + c * 4);
        ull acc0, acc1, acc2, acc3;
        MUL2(acc0, s0.x, pinv); MUL2(acc1, s0.y, pinv);
        MUL2(acc2, s1.x, pinv); MUL2(acc3, s1.y, pinv);

        #pragma unroll 4
        for (int j = beg; j < end; j++) {
            int2 ed = __ldg(&g_edge[j]);
            ull ww; DUPR(ww, (unsigned)ed.y);
            const float* hp = x + (size_t)ed.x * 64;
            ulonglong2 h0 = *(const ulonglong2*)(hp + c * 4);
            ulonglong2 h1 = *(const ulonglong2*)(hp + 32 + c * 4);
            FMA2(acc0, ww, h0.x); FMA2(acc1, ww, h0.y);
            FMA2(acc2, ww, h1.x); FMA2(acc3, ww, h1.y);
        }
        *(ulonglong2*)&Xs[r * 68 + c * 4]      = make_ulonglong2(acc0, acc1);
        *(ulonglong2*)&Xs[r * 68 + 32 + c * 4] = make_ulonglong2(acc2, acc3);

        // embedding passthrough + state re-zero (independent of smem)
        if (c == 0) g_cnt[node] = 0;
        const float4* src = (node < NU) ? (const float4*)&ue[(size_t)node * 64]
                                        : (const float4*)&ie[(size_t)(node - NU) * 64];
        size_t drow = (node < NU) ? (size_t)(NU + node) : (size_t)(2 * NU + NI + (node - NU));
        float4* dst = (float4*)&out[drow * 64];
        dst[2 * c]     = src[2 * c];
        dst[2 * c + 1] = src[2 * c + 1];
    }
    __syncthreads();

    // ---- GEMM phase: thread -> (row r, cols c*8 .. c*8+7) ----
    int cb = c << 3;
    ull acc[4];
    {
        float un1 = (node < NN) ? g_u1[node] : 0.f;
        float un2 = (node < NN) ? g_u2[node] : 0.f;
        #pragma unroll
        for (int i = 0; i < 4; i++) {
            float lo = b3[cb + 2 * i]     + un2 * g_bv2[cb + 2 * i]     + un1 * g_bv1[cb + 2 * i];
            float hi = b3[cb + 2 * i + 1] + un2 * g_bv2[cb + 2 * i + 1] + un1 * g_bv1[cb + 2 * i + 1];
            asm("mov.b64 %0, {%1, %2};" : "=l"(acc[i]) : "f"(lo), "f"(hi));
        }
    }
    #pragma unroll
    for (int k = 0; k < 64; k++) {
        float xv = Xs[r * 68 + k];
        ull xvv; DUPF(xvv, xv);
        const ulonglong2* wp = (const ulonglong2*)&Ws[k * 64 + cb];
        ulonglong2 wa = wp[0], wb2 = wp[1];
        FMA2(acc[0], xvv, wa.x);
        FMA2(acc[1], xvv, wa.y);
        FMA2(acc[2], xvv, wb2.x);
        FMA2(acc[3], xvv, wb2.y);
    }
    if (node < NN) {
        int orow = (node < NU) ? node : node + NU;
        ulonglong2* o = (ulonglong2*)&out[(size_t)orow * 64 + cb];
        o[0] = make_ulonglong2(acc[0], acc[1]);
        o[1] = make_ulonglong2(acc[2], acc[3]);
    }
}

// ---------------------------------------------------------------------------
extern "C" void kernel_launch(void* const* d_in, const int* in_sizes, int n_in,
                              void* d_out, int out_size) {
    const int*   ei = (const int*)d_in[0];
    const float* ue = (const float*)d_in[1];
    const float* ie = (const float*)d_in[2];
    const float* Ws = (const float*)d_in[3];
    const float* bs = (const float*)d_in[4];
    float* out = (float*)d_out;

    float *bufA, *bufB, *u1, *u2;
    cudaGetSymbolAddress((void**)&bufA, g_bufA);
    cudaGetSymbolAddress((void**)&bufB, g_bufB);
    cudaGetSymbolAddress((void**)&u1,   g_u1);
    cudaGetSymbolAddress((void**)&u2,   g_u2);

    const int TB = 256;
    const int AGG_GRID = (NN * 8 + TB - 1) / TB;   // ceil (4688)
    k_deg       <<<(NE + TB - 1) / TB, TB>>>(ei);                                   // 1
    k_scan_wprod<<<NBLK + 1, SCAN_B>>>(Ws, bs);                                     // 2
    k_fill      <<<(NE + TB - 1) / TB, TB>>>(ei);                                   // 3
    k_agg<true,  false, true ><<<AGG_GRID, TB>>>(ue, ie, nullptr, u1, bufA);        // 4 <- profiled
    k_agg<false, true,  true ><<<AGG_GRID, TB>>>(bufA, bufA, u1, u2, bufB);         // 5
    k_agg_gemm  <<<(NN + 31) / 32, TB>>>(bufB, bs + 2 * 64, ue, ie, out);           // 6
}

// round 11
// speedup vs baseline: 1.4692x; 1.4692x over previous
#include <cuda_runtime.h>

#define NU 100000
#define NI 50000
#define NN 150000
#define HD 64
#define NE 1200000
#define SCAN_B 1024
#define NBLK ((NN + SCAN_B - 1) / SCAN_B)   // 147

typedef unsigned long long ull;

// Scratch (static device globals; zero-initialized at load)
__device__ float g_bufA[NN * HD];
__device__ float g_bufB[NN * HD];
__device__ float g_u1[NN];
__device__ float g_u2[NN];
__device__ float g_dinv[NN];
__device__ int   g_cnt[NN];          // edge in-degree (self loop NOT included)
__device__ int   g_flag[NBLK];       // scan: total+1 (0 = not ready)
__device__ int   g_off[NN + 1];
__device__ int   g_cur[NN];
__device__ int2  g_edge[NE];         // {src, norm bits}, bucketed by dst
__device__ float g_W123[HD * HD];    // W1@W2@W3
__device__ float g_bv1[HD];          // b2@W3
__device__ float g_bv2[HD];          // b1@W2@W3

#define FMA2(acc, a, b) \
    asm("fma.rn.f32x2 %0, %1, %2, %0;" : "+l"(acc) : "l"(a), "l"(b))
#define MUL2(d, a, b) \
    asm("mul.rn.f32x2 %0, %1, %2;" : "=l"(d) : "l"(a), "l"(b))
#define ADD2(d, a, b) \
    asm("add.rn.f32x2 %0, %1, %2;" : "=l"(d) : "l"(a), "l"(b))
#define DUPF(d, f) \
    asm("mov.b64 %0, {%1, %1};" : "=l"(d) : "f"(f))
#define DUPR(d, r) \
    asm("mov.b64 %0, {%1, %1};" : "=l"(d) : "r"(r))

// ---------------------------------------------------------------------------
// Degree count
// ---------------------------------------------------------------------------
__global__ void k_deg(const int* __restrict__ ei) {
    int e = blockIdx.x * blockDim.x + threadIdx.x;
    if (e < NE) atomicAdd(&g_cnt[ei[NE + e]], 1);
}

// ---------------------------------------------------------------------------
// Fused: blocks 0..NBLK-1 = single-pass scan of g_cnt (all co-resident,
// decoupled-lookback-lite via g_flag) + dinv; block NBLK = weight products.
// ---------------------------------------------------------------------------
__global__ void __launch_bounds__(1024)
k_scan_wprod(const float* __restrict__ Wsrc, const float* __restrict__ bs) {
    __shared__ float smem[3 * 4096 + 64];
    int tid = threadIdx.x;

    if (blockIdx.x < NBLK) {
        // ---- scan part ----
        int* ws    = (int*)smem;
        int* basep = (int*)smem + 40;
        if (tid == 0) *basep = 0;
        int i = blockIdx.x * SCAN_B + tid;
        int lane = tid & 31, wid = tid >> 5;
        int cnt = (i < NN) ? g_cnt[i] : 0;
        if (i < NN) g_dinv[i] = rsqrtf((float)(cnt + 1));
        int x = cnt;
        #pragma unroll
        for (int o = 1; o < 32; o <<= 1) {
            int y = __shfl_up_sync(0xffffffffu, x, o);
            if (lane >= o) x += y;
        }
        if (lane == 31) ws[wid] = x;
        __syncthreads();
        if (wid == 0) {
            int s = ws[lane];
            #pragma unroll
            for (int o = 1; o < 32; o <<= 1) {
                int y = __shfl_up_sync(0xffffffffu, s, o);
                if (lane >= o) s += y;
            }
            ws[lane] = s;
        }
        __syncthreads();
        int incl = x + (wid > 0 ? ws[wid - 1] : 0);

        if (tid == SCAN_B - 1)
            *((volatile int*)&g_flag[blockIdx.x]) = incl + 1;

        if (tid < blockIdx.x) {
            int v;
            do { v = *((volatile int*)&g_flag[tid]); } while (v == 0);
            atomicAdd(basep, v - 1);
        }
        __syncthreads();

        if (i < NN) {
            int g = incl + *basep;
            g_off[i + 1] = g;
            g_cur[i] = g - cnt;
            if (i == 0) g_off[0] = 0;
        }
    } else {
        // ---- wprod part: W123 = W1@W2@W3, bv2 = b1@W2@W3, bv1 = b2@W3 ----
        float* A = smem;
        float* B = smem + 4096;
        float* T = smem + 8192;
        ((float4*)A)[tid] = ((const float4*)(Wsrc + 4096))[tid];   // W2
        ((float4*)B)[tid] = ((const float4*)(Wsrc + 8192))[tid];   // W3
        __syncthreads();
        #pragma unroll
        for (int i = 0; i < 4; i++) {            // T = W2@W3
            int idx = tid * 4 + i, r = idx >> 6, c = idx & 63;
            float s = 0.f;
            #pragma unroll
            for (int k = 0; k < 64; k++) s += A[r * 64 + k] * B[k * 64 + c];
            T[idx] = s;
        }
        __syncthreads();
        ((float4*)A)[tid] = ((const float4*)Wsrc)[tid];            // W1
        __syncthreads();
        #pragma unroll
        for (int i = 0; i < 4; i++) {            // W123 = W1@T
            int idx = tid * 4 + i, r = idx >> 6, c = idx & 63;
            float s = 0.f;
            #pragma unroll
            for (int k = 0; k < 64; k++) s += A[r * 64 + k] * T[k * 64 + c];
            g_W123[idx] = s;
        }
        if (tid < 64) {                          // bv2 = b1@T
            float s = 0.f;
            #pragma unroll
            for (int k = 0; k < 64; k++) s += bs[k] * T[k * 64 + tid];
            g_bv2[tid] = s;
        } else if (tid < 128) {                  // bv1 = b2@W3
            int c = tid - 64;
            float s = 0.f;
            #pragma unroll
            for (int k = 0; k < 64; k++) s += bs[64 + k] * B[k * 64 + c];
            g_bv1[c] = s;
        }
    }
}

// ---------------------------------------------------------------------------
// Bucket fill (norm from precomputed dinv)
// ---------------------------------------------------------------------------
__global__ void k_fill(const int* __restrict__ ei) {
    int e = blockIdx.x * blockDim.x + threadIdx.x;
    if (e >= NE) return;
    int s = ei[e];
    int d = ei[NE + e];
    float nrm = g_dinv[s] * g_dinv[d];
    int pos = atomicAdd(&g_cur[d], 1);
    g_edge[pos] = make_int2(s, __float_as_int(nrm));
}

// ---------------------------------------------------------------------------
// Aggregation core loop (R9 shuffle scheme + dual accumulator chains).
// Lane c of an 8-lane group owns cols [4c,4c+4) and [32+4c,32+4c+4).
// Batch of 8 edges preloaded (one per lane), broadcast by width-8 shuffle;
// steps processed in pairs into independent accA/accB chains.
// ---------------------------------------------------------------------------
#define AGG_BODY(PTR_OF)                                                      \
    ull a0, a1, a2, a3, b0 = 0, b1 = 0, b2 = 0, b3 = 0;                       \
    MUL2(a0, s0.x, pinv); MUL2(a1, s0.y, pinv);                               \
    MUL2(a2, s1.x, pinv); MUL2(a3, s1.y, pinv);                               \
    int idx = beg + c;                                                        \
    int2 ed = (idx < end) ? g_edge[idx] : make_int2(0, 0);                    \
    for (int j0 = beg; j0 < end; j0 += 8) {                                   \
        int nidx = j0 + 8 + c;                                                \
        int2 edn = (nidx < end) ? g_edge[nidx] : make_int2(0, 0);             \
        UACC_STEP                                                             \
        _Pragma("unroll")                                                     \
        for (int k = 0; k < 8; k += 2) {                                      \
            int      sa = __shfl_sync(gmask, ed.x, k, 8);                     \
            unsigned wa = (unsigned)__shfl_sync(gmask, ed.y, k, 8);           \
            int      sb = __shfl_sync(gmask, ed.x, k + 1, 8);                 \
            unsigned wb = (unsigned)__shfl_sync(gmask, ed.y, k + 1, 8);       \
            const float* pa = PTR_OF(sa);                                     \
            const float* pb = PTR_OF(sb);                                     \
            ulonglong2 ha0 = *(const ulonglong2*)(pa + c * 4);                \
            ulonglong2 ha1 = *(const ulonglong2*)(pa + 32 + c * 4);           \
            ulonglong2 hb0 = *(const ulonglong2*)(pb + c * 4);                \
            ulonglong2 hb1 = *(const ulonglong2*)(pb + 32 + c * 4);           \
            ull wwa; DUPR(wwa, wa);                                           \
            ull wwb; DUPR(wwb, wb);                                           \
            FMA2(a0, wwa, ha0.x); FMA2(a1, wwa, ha0.y);                       \
            FMA2(a2, wwa, ha1.x); FMA2(a3, wwa, ha1.y);                       \
            FMA2(b0, wwb, hb0.x); FMA2(b1, wwb, hb0.y);                       \
            FMA2(b2, wwb, hb1.x); FMA2(b3, wwb, hb1.y);                       \
        }                                                                     \
        ed = edn;                                                             \
    }                                                                         \
    ADD2(a0, a0, b0); ADD2(a1, a1, b1);                                       \
    ADD2(a2, a2, b2); ADD2(a3, a3, b3);

// ---------------------------------------------------------------------------
template<bool SPLIT, bool UIN, bool UOUT>
__global__ void k_agg(const float* __restrict__ xA, const float* __restrict__ xB,
                      const float* __restrict__ u_in, float* __restrict__ u_out,
                      float* __restrict__ y) {
    int t = blockIdx.x * blockDim.x + threadIdx.x;
    int node = t >> 3;
    int c = t & 7;
    if (node >= NN) return;
    unsigned gmask = 0xFFu << (threadIdx.x & 24);

    int beg = g_off[node];
    int end = g_off[node + 1];
    float inv = 1.0f / (float)(end - beg + 1);
    ull pinv; DUPF(pinv, inv);

    const float* selfp = SPLIT ? (node < NU ? xA + (size_t)node * 64
                                            : xB + (size_t)(node - NU) * 64)
                               : xA + (size_t)node * 64;
    ulonglong2 s0 = *(const ulonglong2*)(selfp + c * 4);
    ulonglong2 s1 = *(const ulonglong2*)(selfp + 32 + c * 4);
    float uacc = 0.0f;

    #define PTR_OF(s) (SPLIT ? ((s) < NU ? xA + (size_t)(s) * 64               \
                                         : xB + (size_t)((s) - NU) * 64)       \
                             : xA + (size_t)(s) * 64)
    #define UACC_STEP                                                          \
        if (UOUT && (j0 + c) < end)                                            \
            uacc += __int_as_float(ed.y) * (UIN ? u_in[ed.x] : 1.0f);
    AGG_BODY(PTR_OF)
    #undef PTR_OF
    #undef UACC_STEP

    *(ulonglong2*)(y + (size_t)node * 64 + c * 4)      = make_ulonglong2(a0, a1);
    *(ulonglong2*)(y + (size_t)node * 64 + 32 + c * 4) = make_ulonglong2(a2, a3);

    if (UOUT) {
        #pragma unroll
        for (int o = 4; o > 0; o >>= 1)
            uacc += __shfl_down_sync(gmask, uacc, o, 8);
        if (c == 0) u_out[node] = uacc + inv * (UIN ? u_in[node] : 1.0f);
    }
}

// ---------------------------------------------------------------------------
// Fused agg3 + final GEMM:
//   y3 = A~ @ x staged in smem; out[remap] = y3@W123 + u2*bv2 + u1*bv1 + b3.
// Also copies raw embeddings to out segments 1/3 and re-zeroes g_cnt/g_flag.
// 256 threads = 32 nodes x 8 lanes; GEMM reuses the same row mapping.
// ---------------------------------------------------------------------------
__global__ void k_agg_gemm(const float* __restrict__ x, const float* __restrict__ b3,
                           const float* __restrict__ ue, const float* __restrict__ ie,
                           float* __restrict__ out) {
    __shared__ float Ws[64 * 64];
    __shared__ float Xs[32 * 68];
    int tid  = threadIdx.x;
    int row0 = blockIdx.x * 32;
    int r = tid >> 3;
    int c = tid & 7;
    int node = row0 + r;
    unsigned gmask = 0xFFu << (threadIdx.x & 24);

    #pragma unroll
    for (int i = 0; i < 4; i++)
        ((float4*)Ws)[tid + i * 256] = ((const float4*)g_W123)[tid + i * 256];

    if (blockIdx.x == 0 && tid < NBLK) g_flag[tid] = 0;

    if (node < NN) {
        int beg = g_off[node];
        int end = g_off[node + 1];
        float inv = 1.0f / (float)(end - beg + 1);
        ull pinv; DUPF(pinv, inv);

        const float* selfp = x + (size_t)node * 64;
        ulonglong2 s0 = *(const ulonglong2*)(selfp + c * 4);
        ulonglong2 s1 = *(const ulonglong2*)(selfp + 32 + c * 4);

        #define PTR_OF(s) (x + (size_t)(s) * 64)
        #define UACC_STEP
        AGG_BODY(PTR_OF)
        #undef PTR_OF
        #undef UACC_STEP

        *(ulonglong2*)&Xs[r * 68 + c * 4]      = make_ulonglong2(a0, a1);
        *(ulonglong2*)&Xs[r * 68 + 32 + c * 4] = make_ulonglong2(a2, a3);

        // embedding passthrough + state re-zero (independent of smem)
        if (c == 0) g_cnt[node] = 0;
        const float4* src = (node < NU) ? (const float4*)&ue[(size_t)node * 64]
                                        : (const float4*)&ie[(size_t)(node - NU) * 64];
        size_t drow = (node < NU) ? (size_t)(NU + node) : (size_t)(2 * NU + NI + (node - NU));
        float4* dst = (float4*)&out[drow * 64];
        dst[2 * c]     = src[2 * c];
        dst[2 * c + 1] = src[2 * c + 1];
    }
    __syncthreads();

    // ---- GEMM phase: thread -> (row r, cols c*8 .. c*8+7) ----
    int cb = c << 3;
    ull acc[4];
    {
        float un1 = (node < NN) ? g_u1[node] : 0.f;
        float un2 = (node < NN) ? g_u2[node] : 0.f;
        #pragma unroll
        for (int i = 0; i < 4; i++) {
            float lo = b3[cb + 2 * i]     + un2 * g_bv2[cb + 2 * i]     + un1 * g_bv1[cb + 2 * i];
            float hi = b3[cb + 2 * i + 1] + un2 * g_bv2[cb + 2 * i + 1] + un1 * g_bv1[cb + 2 * i + 1];
            asm("mov.b64 %0, {%1, %2};" : "=l"(acc[i]) : "f"(lo), "f"(hi));
        }
    }
    #pragma unroll
    for (int k = 0; k < 64; k++) {
        float xv = Xs[r * 68 + k];
        ull xvv; DUPF(xvv, xv);
        const ulonglong2* wp = (const ulonglong2*)&Ws[k * 64 + cb];
        ulonglong2 wa = wp[0], wb2 = wp[1];
        FMA2(acc[0], xvv, wa.x);
        FMA2(acc[1], xvv, wa.y);
        FMA2(acc[2], xvv, wb2.x);
        FMA2(acc[3], xvv, wb2.y);
    }
    if (node < NN) {
        int orow = (node < NU) ? node : node + NU;
        ulonglong2* o = (ulonglong2*)&out[(size_t)orow * 64 + cb];
        o[0] = make_ulonglong2(acc[0], acc[1]);
        o[1] = make_ulonglong2(acc[2], acc[3]);
    }
}

// ---------------------------------------------------------------------------
extern "C" void kernel_launch(void* const* d_in, const int* in_sizes, int n_in,
                              void* d_out, int out_size) {
    const int*   ei = (const int*)d_in[0];
    const float* ue = (const float*)d_in[1];
    const float* ie = (const float*)d_in[2];
    const float* Ws = (const float*)d_in[3];
    const float* bs = (const float*)d_in[4];
    float* out = (float*)d_out;

    float *bufA, *bufB, *u1, *u2;
    cudaGetSymbolAddress((void**)&bufA, g_bufA);
    cudaGetSymbolAddress((void**)&bufB, g_bufB);
    cudaGetSymbolAddress((void**)&u1,   g_u1);
    cudaGetSymbolAddress((void**)&u2,   g_u2);

    const int TB = 256;
    const int AGG_GRID = (NN * 8 + TB - 1) / TB;   // ceil (4688)
    k_deg       <<<(NE + TB - 1) / TB, TB>>>(ei);                                   // 1
    k_scan_wprod<<<NBLK + 1, SCAN_B>>>(Ws, bs);                                     // 2
    k_fill      <<<(NE + TB - 1) / TB, TB>>>(ei);                                   // 3
    k_agg<true,  false, true ><<<AGG_GRID, TB>>>(ue, ie, nullptr, u1, bufA);        // 4 <- profiled
    k_agg<false, true,  true ><<<AGG_GRID, TB>>>(bufA, bufA, u1, u2, bufB);         // 5
    k_agg_gemm  <<<(NN + 31) / 32, TB>>>(bufB, bs + 2 * 64, ue, ie, out);           // 6
}

// round 12
// speedup vs baseline: 1.5393x; 1.0477x over previous
#include <cuda_runtime.h>

#define NU 100000
#define NI 50000
#define NN 150000
#define HD 64
#define NE 1200000
#define SCAN_B 1024
#define NBLK ((NN + SCAN_B - 1) / SCAN_B)   // 147

typedef unsigned long long ull;

// Scratch (static device globals; zero-initialized at load).
// bufA/bufB/v1 have a zero row/slot at index NN (never written) used as
// padding target so out-of-range edge slots are exact no-ops.
__device__ float g_bufA[(NN + 1) * HD];   // z1 = dinv . (A~ x0)
__device__ float g_bufB[(NN + 1) * HD];   // z2 = dinv . (A~^2 x0)
__device__ float g_u1[NN];                // A~ 1
__device__ float g_v1[NN + 1];            // dinv * u1
__device__ float g_u2[NN];                // A~^2 1
__device__ float g_dinv[NN];
__device__ int   g_cnt[NN];               // edge in-degree (no self loop)
__device__ int   g_flag[NBLK];            // scan: total+1 (0 = not ready)
__device__ int   g_off[NN + 1];
__device__ int   g_cur[NN];
__device__ int   g_edge[NE];              // src index only, bucketed by dst
__device__ float g_W123[HD * HD];         // W1@W2@W3
__device__ float g_bv1[HD];               // b2@W3
__device__ float g_bv2[HD];               // b1@W2@W3

#define FMA2(acc, a, b) \
    asm("fma.rn.f32x2 %0, %1, %2, %0;" : "+l"(acc) : "l"(a), "l"(b))
#define MUL2(d, a, b) \
    asm("mul.rn.f32x2 %0, %1, %2;" : "=l"(d) : "l"(a), "l"(b))
#define ADD2(acc, b) \
    asm("add.rn.f32x2 %0, %0, %1;" : "+l"(acc) : "l"(b))
#define DUPF(d, f) \
    asm("mov.b64 %0, {%1, %1};" : "=l"(d) : "f"(f))

// ---------------------------------------------------------------------------
__global__ void k_deg(const int* __restrict__ ei) {
    int e = blockIdx.x * blockDim.x + threadIdx.x;
    if (e < NE) atomicAdd(&g_cnt[ei[NE + e]], 1);
}

// ---------------------------------------------------------------------------
// Fused: blocks 0..NBLK-1 = single-pass scan of g_cnt + dinv;
// block NBLK = weight/bias products.
// ---------------------------------------------------------------------------
__global__ void __launch_bounds__(1024)
k_scan_wprod(const float* __restrict__ Wsrc, const float* __restrict__ bs) {
    __shared__ float smem[3 * 4096 + 64];
    int tid = threadIdx.x;

    if (blockIdx.x < NBLK) {
        int* ws    = (int*)smem;
        int* basep = (int*)smem + 40;
        if (tid == 0) *basep = 0;
        int i = blockIdx.x * SCAN_B + tid;
        int lane = tid & 31, wid = tid >> 5;
        int cnt = (i < NN) ? g_cnt[i] : 0;
        if (i < NN) g_dinv[i] = rsqrtf((float)(cnt + 1));
        int x = cnt;
        #pragma unroll
        for (int o = 1; o < 32; o <<= 1) {
            int y = __shfl_up_sync(0xffffffffu, x, o);
            if (lane >= o) x += y;
        }
        if (lane == 31) ws[wid] = x;
        __syncthreads();
        if (wid == 0) {
            int s = ws[lane];
            #pragma unroll
            for (int o = 1; o < 32; o <<= 1) {
                int y = __shfl_up_sync(0xffffffffu, s, o);
                if (lane >= o) s += y;
            }
            ws[lane] = s;
        }
        __syncthreads();
        int incl = x + (wid > 0 ? ws[wid - 1] : 0);

        if (tid == SCAN_B - 1)
            *((volatile int*)&g_flag[blockIdx.x]) = incl + 1;

        if (tid < blockIdx.x) {
            int v;
            do { v = *((volatile int*)&g_flag[tid]); } while (v == 0);
            atomicAdd(basep, v - 1);
        }
        __syncthreads();

        if (i < NN) {
            int g = incl + *basep;
            g_off[i + 1] = g;
            g_cur[i] = g - cnt;
            if (i == 0) g_off[0] = 0;
        }
    } else {
        float* A = smem;
        float* B = smem + 4096;
        float* T = smem + 8192;
        ((float4*)A)[tid] = ((const float4*)(Wsrc + 4096))[tid];   // W2
        ((float4*)B)[tid] = ((const float4*)(Wsrc + 8192))[tid];   // W3
        __syncthreads();
        #pragma unroll
        for (int i = 0; i < 4; i++) {            // T = W2@W3
            int idx = tid * 4 + i, r = idx >> 6, c = idx & 63;
            float s = 0.f;
            #pragma unroll
            for (int k = 0; k < 64; k++) s += A[r * 64 + k] * B[k * 64 + c];
            T[idx] = s;
        }
        __syncthreads();
        ((float4*)A)[tid] = ((const float4*)Wsrc)[tid];            // W1
        __syncthreads();
        #pragma unroll
        for (int i = 0; i < 4; i++) {            // W123 = W1@T
            int idx = tid * 4 + i, r = idx >> 6, c = idx & 63;
            float s = 0.f;
            #pragma unroll
            for (int k = 0; k < 64; k++) s += A[r * 64 + k] * T[k * 64 + c];
            g_W123[idx] = s;
        }
        if (tid < 64) {                          // bv2 = b1@T
            float s = 0.f;
            #pragma unroll
            for (int k = 0; k < 64; k++) s += bs[k] * T[k * 64 + tid];
            g_bv2[tid] = s;
        } else if (tid < 128) {                  // bv1 = b2@W3
            int c = tid - 64;
            float s = 0.f;
            #pragma unroll
            for (int k = 0; k < 64; k++) s += bs[64 + k] * B[k * 64 + c];
            g_bv1[c] = s;
        }
    }
}

// ---------------------------------------------------------------------------
// Bucket fill: 4-byte src index only
// ---------------------------------------------------------------------------
__global__ void k_fill(const int* __restrict__ ei) {
    int e = blockIdx.x * blockDim.x + threadIdx.x;
    if (e >= NE) return;
    int s = ei[e];
    int d = ei[NE + e];
    int pos = atomicAdd(&g_cur[d], 1);
    g_edge[pos] = s;
}

// ---------------------------------------------------------------------------
// agg1: z1[d] = dinv_d^2 * ( sum_e dinv_s * x0[s] + dinv_d * x0[d] )
//       u1[d] = dinv_d * ( sum_e dinv_s + dinv_d );  v1 = dinv_d * u1
// 8 lanes/node; lane c owns cols {4c..4c+3, 32+4c..32+4c+3}.
// ---------------------------------------------------------------------------
__global__ void k_agg1(const float* __restrict__ ue, const float* __restrict__ ie,
                       float* __restrict__ y) {
    int t = blockIdx.x * blockDim.x + threadIdx.x;
    int node = t >> 3;
    int c = t & 7;
    if (node >= NN) return;
    unsigned gmask = 0xFFu << (threadIdx.x & 24);

    int beg = g_off[node];
    int end = g_off[node + 1];
    float dv = rsqrtf((float)(end - beg + 1));
    ull pdv; DUPF(pdv, dv);

    const float* selfp = (node < NU) ? ue + (size_t)node * 64
                                     : ie + (size_t)(node - NU) * 64;
    ulonglong2 s0 = *(const ulonglong2*)(selfp + c * 4);
    ulonglong2 s1 = *(const ulonglong2*)(selfp + 32 + c * 4);
    ull a0, a1, a2, a3;
    MUL2(a0, s0.x, pdv); MUL2(a1, s0.y, pdv);
    MUL2(a2, s1.x, pdv); MUL2(a3, s1.y, pdv);
    float uacc = 0.0f;

    int idx = beg + c;
    int   ed = (idx < end) ? g_edge[idx] : 0;
    float wv = (idx < end) ? g_dinv[ed] : 0.0f;
    for (int j0 = beg; j0 < end; j0 += 8) {
        int nidx = j0 + 8 + c;
        int   edn = (nidx < end) ? g_edge[nidx] : 0;
        float wn  = (nidx < end) ? g_dinv[edn] : 0.0f;
        uacc += wv;
        #pragma unroll
        for (int k = 0; k < 8; k++) {
            int   s = __shfl_sync(gmask, ed, k, 8);
            float w = __shfl_sync(gmask, wv, k, 8);
            ull ww; DUPF(ww, w);
            const float* hp = (s < NU) ? ue + (size_t)s * 64
                                       : ie + (size_t)(s - NU) * 64;
            ulonglong2 h0 = *(const ulonglong2*)(hp + c * 4);
            ulonglong2 h1 = *(const ulonglong2*)(hp + 32 + c * 4);
            FMA2(a0, ww, h0.x); FMA2(a1, ww, h0.y);
            FMA2(a2, ww, h1.x); FMA2(a3, ww, h1.y);
        }
        ed = edn; wv = wn;
    }

    float dv2 = dv * dv;
    ull pdv2; DUPF(pdv2, dv2);
    MUL2(a0, a0, pdv2); MUL2(a1, a1, pdv2);
    MUL2(a2, a2, pdv2); MUL2(a3, a3, pdv2);
    *(ulonglong2*)(y + (size_t)node * 64 + c * 4)      = make_ulonglong2(a0, a1);
    *(ulonglong2*)(y + (size_t)node * 64 + 32 + c * 4) = make_ulonglong2(a2, a3);

    #pragma unroll
    for (int o = 4; o > 0; o >>= 1)
        uacc += __shfl_down_sync(gmask, uacc, o, 8);
    if (c == 0) {
        float u1 = dv * (uacc + dv);
        g_u1[node] = u1;
        g_v1[node] = dv * u1;
    }
}

// ---------------------------------------------------------------------------
// agg2: z2[d] = dinv_d^2 * ( sum_e z1[s] + z1[d] )   (unweighted adds)
//       u2[d] = dinv_d * ( sum_e v1[s] + v1[d] )
// Padding edges point at zero row NN -> exact no-op.
// ---------------------------------------------------------------------------
__global__ void k_agg2(const float* __restrict__ x, float* __restrict__ y) {
    int t = blockIdx.x * blockDim.x + threadIdx.x;
    int node = t >> 3;
    int c = t & 7;
    if (node >= NN) return;
    unsigned gmask = 0xFFu << (threadIdx.x & 24);

    int beg = g_off[node];
    int end = g_off[node + 1];
    float dv = rsqrtf((float)(end - beg + 1));

    const float* selfp = x + (size_t)node * 64;
    ulonglong2 s0 = *(const ulonglong2*)(selfp + c * 4);
    ulonglong2 s1 = *(const ulonglong2*)(selfp + 32 + c * 4);
    ull a0 = s0.x, a1 = s0.y, a2 = s1.x, a3 = s1.y;
    float uacc = 0.0f;

    int idx = beg + c;
    int ed = (idx < end) ? g_edge[idx] : NN;
    for (int j0 = beg; j0 < end; j0 += 8) {
        int nidx = j0 + 8 + c;
        int edn = (nidx < end) ? g_edge[nidx] : NN;
        uacc += g_v1[ed];                      // v1[NN] == 0
        #pragma unroll
        for (int k = 0; k < 8; k++) {
            int s = __shfl_sync(gmask, ed, k, 8);
            const float* hp = x + (size_t)s * 64;
            ulonglong2 h0 = *(const ulonglong2*)(hp + c * 4);
            ulonglong2 h1 = *(const ulonglong2*)(hp + 32 + c * 4);
            ADD2(a0, h0.x); ADD2(a1, h0.y);
            ADD2(a2, h1.x); ADD2(a3, h1.y);
        }
        ed = edn;
    }

    float dv2 = dv * dv;
    ull pdv2; DUPF(pdv2, dv2);
    MUL2(a0, a0, pdv2); MUL2(a1, a1, pdv2);
    MUL2(a2, a2, pdv2); MUL2(a3, a3, pdv2);
    *(ulonglong2*)(y + (size_t)node * 64 + c * 4)      = make_ulonglong2(a0, a1);
    *(ulonglong2*)(y + (size_t)node * 64 + 32 + c * 4) = make_ulonglong2(a2, a3);

    #pragma unroll
    for (int o = 4; o > 0; o >>= 1)
        uacc += __shfl_down_sync(gmask, uacc, o, 8);
    if (c == 0) g_u2[node] = dv * (uacc + g_v1[node]);
}

// ---------------------------------------------------------------------------
// Fused agg3 + final GEMM:
//   y3[d] = dinv_d * ( sum_e z2[s] + z2[d] )   staged in smem,
//   out[remap] = y3@W123 + u2*bv2 + u1*bv1 + b3.
// Also copies raw embeddings to out segments 1/3 and re-zeroes g_cnt/g_flag.
// ---------------------------------------------------------------------------
__global__ void k_agg_gemm(const float* __restrict__ x, const float* __restrict__ b3,
                           const float* __restrict__ ue, const float* __restrict__ ie,
                           float* __restrict__ out) {
    __shared__ float Ws[64 * 64];
    __shared__ float Xs[32 * 68];
    int tid  = threadIdx.x;
    int row0 = blockIdx.x * 32;
    int r = tid >> 3;
    int c = tid & 7;
    int node = row0 + r;
    unsigned gmask = 0xFFu << (threadIdx.x & 24);

    #pragma unroll
    for (int i = 0; i < 4; i++)
        ((float4*)Ws)[tid + i * 256] = ((const float4*)g_W123)[tid + i * 256];

    if (blockIdx.x == 0 && tid < NBLK) g_flag[tid] = 0;

    if (node < NN) {
        int beg = g_off[node];
        int end = g_off[node + 1];
        float dv = rsqrtf((float)(end - beg + 1));

        const float* selfp = x + (size_t)node * 64;
        ulonglong2 s0 = *(const ulonglong2*)(selfp + c * 4);
        ulonglong2 s1 = *(const ulonglong2*)(selfp + 32 + c * 4);
        ull a0 = s0.x, a1 = s0.y, a2 = s1.x, a3 = s1.y;

        int idx = beg + c;
        int ed = (idx < end) ? g_edge[idx] : NN;
        for (int j0 = beg; j0 < end; j0 += 8) {
            int nidx = j0 + 8 + c;
            int edn = (nidx < end) ? g_edge[nidx] : NN;
            #pragma unroll
            for (int k = 0; k < 8; k++) {
                int s = __shfl_sync(gmask, ed, k, 8);
                const float* hp = x + (size_t)s * 64;
                ulonglong2 h0 = *(const ulonglong2*)(hp + c * 4);
                ulonglong2 h1 = *(const ulonglong2*)(hp + 32 + c * 4);
                ADD2(a0, h0.x); ADD2(a1, h0.y);
                ADD2(a2, h1.x); ADD2(a3, h1.y);
            }
            ed = edn;
        }
        ull pdv; DUPF(pdv, dv);
        MUL2(a0, a0, pdv); MUL2(a1, a1, pdv);
        MUL2(a2, a2, pdv); MUL2(a3, a3, pdv);
        *(ulonglong2*)&Xs[r * 68 + c * 4]      = make_ulonglong2(a0, a1);
        *(ulonglong2*)&Xs[r * 68 + 32 + c * 4] = make_ulonglong2(a2, a3);

        // embedding passthrough + state re-zero
        if (c == 0) g_cnt[node] = 0;
        const float4* src = (node < NU) ? (const float4*)&ue[(size_t)node * 64]
                                        : (const float4*)&ie[(size_t)(node - NU) * 64];
        size_t drow = (node < NU) ? (size_t)(NU + node) : (size_t)(2 * NU + NI + (node - NU));
        float4* dst = (float4*)&out[drow * 64];
        dst[2 * c]     = src[2 * c];
        dst[2 * c + 1] = src[2 * c + 1];
    }
    __syncthreads();

    // ---- GEMM phase: thread -> (row r, cols c*8 .. c*8+7) ----
    int cb = c << 3;
    ull acc[4];
    {
        float un1 = (node < NN) ? g_u1[node] : 0.f;
        float un2 = (node < NN) ? g_u2[node] : 0.f;
        #pragma unroll
        for (int i = 0; i < 4; i++) {
            float lo = b3[cb + 2 * i]     + un2 * g_bv2[cb + 2 * i]     + un1 * g_bv1[cb + 2 * i];
            float hi = b3[cb + 2 * i + 1] + un2 * g_bv2[cb + 2 * i + 1] + un1 * g_bv1[cb + 2 * i + 1];
            asm("mov.b64 %0, {%1, %2};" : "=l"(acc[i]) : "f"(lo), "f"(hi));
        }
    }
    #pragma unroll
    for (int k = 0; k < 64; k++) {
        float xv = Xs[r * 68 + k];
        ull xvv; DUPF(xvv, xv);
        const ulonglong2* wp = (const ulonglong2*)&Ws[k * 64 + cb];
        ulonglong2 wa = wp[0], wb2 = wp[1];
        FMA2(acc[0], xvv, wa.x);
        FMA2(acc[1], xvv, wa.y);
        FMA2(acc[2], xvv, wb2.x);
        FMA2(acc[3], xvv, wb2.y);
    }
    if (node < NN) {
        int orow = (node < NU) ? node : node + NU;
        ulonglong2* o = (ulonglong2*)&out[(size_t)orow * 64 + cb];
        o[0] = make_ulonglong2(acc[0], acc[1]);
        o[1] = make_ulonglong2(acc[2], acc[3]);
    }
}

// ---------------------------------------------------------------------------
extern "C" void kernel_launch(void* const* d_in, const int* in_sizes, int n_in,
                              void* d_out, int out_size) {
    const int*   ei = (const int*)d_in[0];
    const float* ue = (const float*)d_in[1];
    const float* ie = (const float*)d_in[2];
    const float* Ws = (const float*)d_in[3];
    const float* bs = (const float*)d_in[4];
    float* out = (float*)d_out;

    float *bufA, *bufB;
    cudaGetSymbolAddress((void**)&bufA, g_bufA);
    cudaGetSymbolAddress((void**)&bufB, g_bufB);

    const int TB = 256;
    const int AGG_GRID = (NN * 8 + TB - 1) / TB;   // ceil (4688)
    k_deg       <<<(NE + TB - 1) / TB, TB>>>(ei);              // 1
    k_scan_wprod<<<NBLK + 1, SCAN_B>>>(Ws, bs);                // 2
    k_fill      <<<(NE + TB - 1) / TB, TB>>>(ei);              // 3
    k_agg1      <<<AGG_GRID, TB>>>(ue, ie, bufA);              // 4 <- profiled
    k_agg2      <<<AGG_GRID, TB>>>(bufA, bufB);                // 5
    k_agg_gemm  <<<(NN + 31) / 32, TB>>>(bufB, bs + 2 * 64, ue, ie, out);  // 6
}